// round 15
// baseline (speedup 1.0000x reference)
#include <cuda_runtime.h>
#include <cstdint>

// ---------------------------------------------------------------------------
// VQ-VAE VectorQuantizer, GB300 sm_103 — bit-exact fp32 reference emulation.
// R15: single fused kernel. Codebook-split scorer (2048 blocks = 256 pixel
// groups x 8 chunks, ch = bid&7 so a group's blocks finish together); the
// block completing a group's 8 chunks emits q/idx/loss-partial inline
// (z still in registers); the block completing all groups finalizes the loss
// and resets counters. Scorer arithmetic identical to R13/R14:
//   zz, e2_k: sequential fp32 mul+add chains, c ascending
//   dot_k:    sequential fp32 FMA chain, c ascending (2 codes per FFMA2 lane)
//   d_k = fl(fl(zz+e2_k) - fl(2*dot_k)); first-min, k ascending
//   q   = fl(z + fl(e - z))
// ---------------------------------------------------------------------------

constexpr int CC     = 64;
constexpr int CHW    = 4096;
constexpr int NPIX   = 65536;
constexpr int KCB    = 1024;
constexpr int CHUNK  = 128;          // codes per block
constexpr int NCHUNK = KCB / CHUNK;  // 8
constexpr int NTHR   = 128;
constexpr int GRP    = 256;          // pixels per group (2 per thread)
constexpr int NGRP   = NPIX / GRP;   // 256
constexpr int RS     = 132;          // e_T row stride (floats)

constexpr int Q_ELEMS = 4194304;
constexpr int LOSS0   = Q_ELEMS;
constexpr int LOSS1   = Q_ELEMS + 1;
constexpr int IDX0    = Q_ELEMS + 2;

__device__ float          g_cv[NCHUNK * NPIX];
__device__ unsigned short g_ck[NCHUNK * NPIX];
__device__ float          g_part[NGRP];
__device__ int            g_done[NGRP];   // zero-init; reset by final block
__device__ int            g_all;          // zero-init; reset by final block

// ---- packed f32x2 helpers --------------------------------------------------
__device__ __forceinline__ unsigned long long pack2f(float lo, float hi) {
    unsigned long long r;
    asm("mov.b64 %0, {%1, %2};" : "=l"(r) : "f"(lo), "f"(hi));
    return r;
}
__device__ __forceinline__ void unpack2f(unsigned long long v, float& lo, float& hi) {
    asm("mov.b64 {%0, %1}, %2;" : "=f"(lo), "=f"(hi) : "l"(v));
}
__device__ __forceinline__ unsigned long long ffma2(unsigned long long a,
                                                    unsigned long long b,
                                                    unsigned long long c) {
    unsigned long long d;
    asm("fma.rn.f32x2 %0, %1, %2, %3;" : "=l"(d) : "l"(a), "l"(b), "l"(c));
    return d;
}

__global__ __launch_bounds__(NTHR)
void vq_fused(const float* __restrict__ z, const float* __restrict__ emb,
              float* __restrict__ out) {
    __shared__ __align__(16) float eT[CC * RS];
    __shared__ float e2s[CHUNK];
    __shared__ float reds[NTHR / 32];
    __shared__ int   s_flag, s_fin;

    const int tid = threadIdx.x;
    const int ch  = blockIdx.x & 7;       // chunk (group's 8 blocks adjacent)
    const int grp = blockIdx.x >> 3;

    const int p0  = grp * GRP + tid;
    const int p1  = p0 + NTHR;
    const int b0  = p0 >> 12, hw0 = p0 & 4095;
    const int b1  = p1 >> 12, hw1 = p1 & 4095;
    const float* zp0 = z + (size_t)b0 * (CC * CHW) + hw0;
    const float* zp1 = z + (size_t)b1 * (CC * CHW) + hw1;

    float zr0[CC], zr1[CC];
    #pragma unroll
    for (int c = 0; c < CC; c++) zr0[c] = zp0[c * CHW];
    #pragma unroll
    for (int c = 0; c < CC; c++) zr1[c] = zp1[c * CHW];

    float zz0 = 0.f, zz1 = 0.f;
    #pragma unroll
    for (int c = 0; c < CC; c++) zz0 = __fadd_rn(zz0, __fmul_rn(zr0[c], zr0[c]));
    #pragma unroll
    for (int c = 0; c < CC; c++) zz1 = __fadd_rn(zz1, __fmul_rn(zr1[c], zr1[c]));

    // ---- stage + transpose this chunk into eT[c][k] ------------------------
    const float* ebase = emb + ch * CHUNK * CC;
    #pragma unroll
    for (int it = 0; it < 4; it++) {
        int idx = tid + it * NTHR;        // 0..511
        int k0  = (idx & 31) * 4;
        int c0  = (idx >> 5) * 4;
        float4 r0 = *reinterpret_cast<const float4*>(ebase + (k0 + 0) * CC + c0);
        float4 r1 = *reinterpret_cast<const float4*>(ebase + (k0 + 1) * CC + c0);
        float4 r2 = *reinterpret_cast<const float4*>(ebase + (k0 + 2) * CC + c0);
        float4 r3 = *reinterpret_cast<const float4*>(ebase + (k0 + 3) * CC + c0);
        *reinterpret_cast<float4*>(eT + (c0 + 0) * RS + k0) = make_float4(r0.x, r1.x, r2.x, r3.x);
        *reinterpret_cast<float4*>(eT + (c0 + 1) * RS + k0) = make_float4(r0.y, r1.y, r2.y, r3.y);
        *reinterpret_cast<float4*>(eT + (c0 + 2) * RS + k0) = make_float4(r0.z, r1.z, r2.z, r3.z);
        *reinterpret_cast<float4*>(eT + (c0 + 3) * RS + k0) = make_float4(r0.w, r1.w, r2.w, r3.w);
    }
    __syncthreads();
    {   // exact e2 chain per code (reference mul+add order, c ascending)
        float s = 0.f;
        #pragma unroll
        for (int c = 0; c < CC; c++) {
            float ev = eT[c * RS + tid];
            s = __fadd_rn(s, __fmul_rn(ev, ev));
        }
        e2s[tid] = s;
    }
    __syncthreads();

    float best0 = 3.4e38f, best1 = 3.4e38f;
    int   bk0 = 0, bk1 = 0;

    #pragma unroll 1
    for (int kg = 0; kg < CHUNK / 8; kg++) {
        unsigned long long a00 = 0ull, a01 = 0ull, a02 = 0ull, a03 = 0ull;
        unsigned long long a10 = 0ull, a11 = 0ull, a12 = 0ull, a13 = 0ull;
        const char* rowp = reinterpret_cast<const char*>(eT + kg * 8);
        #pragma unroll
        for (int c = 0; c < CC; c++) {
            const ulonglong2* q =
                reinterpret_cast<const ulonglong2*>(rowp + c * (RS * 4));
            ulonglong2 v0 = q[0];
            ulonglong2 v1 = q[1];
            unsigned long long zd0 = pack2f(zr0[c], zr0[c]);
            unsigned long long zd1 = pack2f(zr1[c], zr1[c]);
            a00 = ffma2(zd0, v0.x, a00);
            a01 = ffma2(zd0, v0.y, a01);
            a02 = ffma2(zd0, v1.x, a02);
            a03 = ffma2(zd0, v1.y, a03);
            a10 = ffma2(zd1, v0.x, a10);
            a11 = ffma2(zd1, v0.y, a11);
            a12 = ffma2(zd1, v1.x, a12);
            a13 = ffma2(zd1, v1.y, a13);
        }
        float d0[8], d1[8];
        unpack2f(a00, d0[0], d0[1]); unpack2f(a01, d0[2], d0[3]);
        unpack2f(a02, d0[4], d0[5]); unpack2f(a03, d0[6], d0[7]);
        unpack2f(a10, d1[0], d1[1]); unpack2f(a11, d1[2], d1[3]);
        unpack2f(a12, d1[4], d1[5]); unpack2f(a13, d1[6], d1[7]);
        int kb = ch * CHUNK + kg * 8;
        #pragma unroll
        for (int j = 0; j < 8; j++) {
            float e2 = e2s[kg * 8 + j];
            float s0 = __fsub_rn(__fadd_rn(zz0, e2), __fmul_rn(2.0f, d0[j]));
            float s1 = __fsub_rn(__fadd_rn(zz1, e2), __fmul_rn(2.0f, d1[j]));
            if (s0 < best0) { best0 = s0; bk0 = kb + j; }
            if (s1 < best1) { best1 = s1; bk1 = kb + j; }
        }
    }

    // ---- publish candidates ------------------------------------------------
    g_cv[ch * NPIX + p0] = best0;
    g_ck[ch * NPIX + p0] = (unsigned short)bk0;
    g_cv[ch * NPIX + p1] = best1;
    g_ck[ch * NPIX + p1] = (unsigned short)bk1;
    __syncthreads();

    // ---- group completion: last of the 8 chunk-blocks emits ----------------
    if (tid == 0) {
        __threadfence();
        s_flag = (atomicAdd(&g_done[grp], 1) == NCHUNK - 1);
    }
    __syncthreads();
    if (!s_flag) return;
    __threadfence();   // acquire: other blocks' candidates visible

    // merge 8 candidates per pixel (ascending chunk, strict < = first-min)
    float bv0 = g_cv[p0];           int fk0 = g_ck[p0];
    float bv1 = g_cv[p1];           int fk1 = g_ck[p1];
    #pragma unroll
    for (int q = 1; q < NCHUNK; q++) {
        float v0 = g_cv[q * NPIX + p0];
        float v1 = g_cv[q * NPIX + p1];
        if (v0 < bv0) { bv0 = v0; fk0 = g_ck[q * NPIX + p0]; }
        if (v1 < bv1) { bv1 = v1; fk1 = g_ck[q * NPIX + p1]; }
    }

    // emit q/idx/loss using the z registers still live
    float sumsq = 0.f;
    {
        const float4* erow = reinterpret_cast<const float4*>(emb + (size_t)fk0 * CC);
        float* qout = out + (size_t)b0 * (CC * CHW) + hw0;
        #pragma unroll
        for (int i = 0; i < CC / 4; i++) {
            float4 e4 = __ldg(erow + i);
            float ev[4] = {e4.x, e4.y, e4.z, e4.w};
            #pragma unroll
            for (int j = 0; j < 4; j++) {
                int c = 4 * i + j;
                float dd = __fsub_rn(ev[j], zr0[c]);
                sumsq = __fadd_rn(sumsq, __fmul_rn(dd, dd));
                qout[c * CHW] = __fadd_rn(zr0[c], dd);
            }
        }
        out[IDX0 + p0] = (float)fk0;
    }
    {
        const float4* erow = reinterpret_cast<const float4*>(emb + (size_t)fk1 * CC);
        float* qout = out + (size_t)b1 * (CC * CHW) + hw1;
        #pragma unroll
        for (int i = 0; i < CC / 4; i++) {
            float4 e4 = __ldg(erow + i);
            float ev[4] = {e4.x, e4.y, e4.z, e4.w};
            #pragma unroll
            for (int j = 0; j < 4; j++) {
                int c = 4 * i + j;
                float dd = __fsub_rn(ev[j], zr1[c]);
                sumsq = __fadd_rn(sumsq, __fmul_rn(dd, dd));
                qout[c * CHW] = __fadd_rn(zr1[c], dd);
            }
        }
        out[IDX0 + p1] = (float)fk1;
    }

    #pragma unroll
    for (int o = 16; o; o >>= 1)
        sumsq += __shfl_xor_sync(0xffffffffu, sumsq, o);
    if ((tid & 31) == 0) reds[tid >> 5] = sumsq;
    __syncthreads();
    if (tid == 0) {
        g_part[grp] = ((reds[0] + reds[1]) + (reds[2] + reds[3]));
        __threadfence();
        s_fin = (atomicAdd(&g_all, 1) == NGRP - 1);
    }
    __syncthreads();
    if (!s_fin) return;
    __threadfence();   // acquire: all g_part visible

    // ---- final block: loss + counter reset (replay-safe) -------------------
    float s = g_part[tid] + g_part[tid + NTHR];   // NGRP = 2*NTHR
    #pragma unroll
    for (int o = 16; o; o >>= 1)
        s += __shfl_xor_sync(0xffffffffu, s, o);
    if ((tid & 31) == 0) reds[tid >> 5] = s;
    g_done[tid] = 0;
    g_done[tid + NTHR] = 0;
    __syncthreads();
    if (tid == 0) {
        float t = ((reds[0] + reds[1]) + (reds[2] + reds[3]));
        float loss = t * (1.0f / (float)Q_ELEMS);
        out[LOSS0] = loss;
        out[LOSS1] = loss;
        g_all = 0;
    }
}

extern "C" void kernel_launch(void* const* d_in, const int* in_sizes, int n_in,
                              void* d_out, int out_size) {
    const float* z   = (const float*)d_in[0];
    const float* emb = (const float*)d_in[1];
    float* out = (float*)d_out;

    vq_fused<<<NCHUNK * NGRP, NTHR>>>(z, emb, out);
}

// round 16
// speedup vs baseline: 1.5652x; 1.5652x over previous
#include <cuda_runtime.h>
#include <cstdint>

// ---------------------------------------------------------------------------
// VQ-VAE VectorQuantizer, GB300 sm_103 — bit-exact fp32 reference emulation.
// R16 = R14 scorer (proven 197.5us, at FFMA2 RF-banking floor) + leaner tail:
// emit regridded to 512x128 with the loss finalize folded into emit's last
// block (counter pattern), deleting the separate vq_fin launch.
//   zz, e2_k: sequential fp32 mul+add chains, c ascending
//   dot_k:    sequential fp32 FMA chain, c ascending (2 codes per FFMA2 lane)
//   d_k = fl(fl(zz+e2_k) - fl(2*dot_k)); first-min, k ascending
//   q   = fl(z + fl(e - z))
// ---------------------------------------------------------------------------

constexpr int CC     = 64;           // channels
constexpr int CHW    = 4096;         // H*W
constexpr int NPIX   = 65536;        // B*H*W
constexpr int KCB    = 1024;         // codebook entries
constexpr int CHUNK  = 128;          // codes per block
constexpr int NCHUNK = KCB / CHUNK;  // 8
constexpr int NTHR   = 128;          // threads per scorer block
constexpr int GRP    = 256;          // pixels per block (PZ=2)
constexpr int NGRP   = NPIX / GRP;   // 256
constexpr int RS     = 132;          // e_T row stride in floats (pad)

constexpr int EBLK   = 512;          // emit grid (128 thr each)

constexpr int Q_ELEMS = 4194304;
constexpr int LOSS0   = Q_ELEMS;
constexpr int LOSS1   = Q_ELEMS + 1;
constexpr int IDX0    = Q_ELEMS + 2;

__device__ float          g_cv[NCHUNK * NPIX];   // candidate scores [ch][px]
__device__ unsigned short g_ck[NCHUNK * NPIX];   // candidate global k
__device__ float          g_part[EBLK];
__device__ int            g_ecnt;                // zero-init; reset below

// ---- packed f32x2 helpers --------------------------------------------------
__device__ __forceinline__ unsigned long long pack2f(float lo, float hi) {
    unsigned long long r;
    asm("mov.b64 %0, {%1, %2};" : "=l"(r) : "f"(lo), "f"(hi));
    return r;
}
__device__ __forceinline__ void unpack2f(unsigned long long v, float& lo, float& hi) {
    asm("mov.b64 {%0, %1}, %2;" : "=f"(lo), "=f"(hi) : "l"(v));
}
__device__ __forceinline__ unsigned long long ffma2(unsigned long long a,
                                                    unsigned long long b,
                                                    unsigned long long c) {
    unsigned long long d;
    asm("fma.rn.f32x2 %0, %1, %2, %3;" : "=l"(d) : "l"(a), "l"(b), "l"(c));
    return d;
}

// ---- K1: per-chunk scorer (256 px x 128 codes per block) — R14 verbatim ----
__global__ __launch_bounds__(NTHR)
void vq_score(const float* __restrict__ z, const float* __restrict__ emb) {
    __shared__ __align__(16) float eT[CC * RS];   // transposed chunk [c][k]
    __shared__ float e2s[CHUNK];

    const int tid = threadIdx.x;
    const int ch  = blockIdx.x >> 8;      // 0..7 (ascending-k chunks)
    const int grp = blockIdx.x & 255;     // 0..255

    const int p0  = grp * GRP + tid;
    const int p1  = p0 + NTHR;
    const int b0  = p0 >> 12, hw0 = p0 & 4095;
    const int b1  = p1 >> 12, hw1 = p1 & 4095;
    const float* zp0 = z + (size_t)b0 * (CC * CHW) + hw0;
    const float* zp1 = z + (size_t)b1 * (CC * CHW) + hw1;

    float zr0[CC], zr1[CC];
    #pragma unroll
    for (int c = 0; c < CC; c++) zr0[c] = zp0[c * CHW];
    #pragma unroll
    for (int c = 0; c < CC; c++) zr1[c] = zp1[c * CHW];

    float zz0 = 0.f, zz1 = 0.f;
    #pragma unroll
    for (int c = 0; c < CC; c++) zz0 = __fadd_rn(zz0, __fmul_rn(zr0[c], zr0[c]));
    #pragma unroll
    for (int c = 0; c < CC; c++) zz1 = __fadd_rn(zz1, __fmul_rn(zr1[c], zr1[c]));

    // ---- stage + transpose this block's chunk into eT[c][k] ---------------
    const float* ebase = emb + ch * CHUNK * CC;
    #pragma unroll
    for (int it = 0; it < 4; it++) {
        int idx = tid + it * NTHR;        // 0..511
        int k0  = (idx & 31) * 4;
        int c0  = (idx >> 5) * 4;
        float4 r0 = *reinterpret_cast<const float4*>(ebase + (k0 + 0) * CC + c0);
        float4 r1 = *reinterpret_cast<const float4*>(ebase + (k0 + 1) * CC + c0);
        float4 r2 = *reinterpret_cast<const float4*>(ebase + (k0 + 2) * CC + c0);
        float4 r3 = *reinterpret_cast<const float4*>(ebase + (k0 + 3) * CC + c0);
        *reinterpret_cast<float4*>(eT + (c0 + 0) * RS + k0) = make_float4(r0.x, r1.x, r2.x, r3.x);
        *reinterpret_cast<float4*>(eT + (c0 + 1) * RS + k0) = make_float4(r0.y, r1.y, r2.y, r3.y);
        *reinterpret_cast<float4*>(eT + (c0 + 2) * RS + k0) = make_float4(r0.z, r1.z, r2.z, r3.z);
        *reinterpret_cast<float4*>(eT + (c0 + 3) * RS + k0) = make_float4(r0.w, r1.w, r2.w, r3.w);
    }
    __syncthreads();
    {   // exact e2 chain per code (reference mul+add order, c ascending)
        float s = 0.f;
        #pragma unroll
        for (int c = 0; c < CC; c++) {
            float ev = eT[c * RS + tid];   // conflict-free (stride 132)
            s = __fadd_rn(s, __fmul_rn(ev, ev));
        }
        e2s[tid] = s;
    }
    __syncthreads();

    float best0 = 3.4e38f, best1 = 3.4e38f;
    int   bk0 = 0, bk1 = 0;

    #pragma unroll 1
    for (int kg = 0; kg < CHUNK / 8; kg++) {
        unsigned long long a00 = 0ull, a01 = 0ull, a02 = 0ull, a03 = 0ull;
        unsigned long long a10 = 0ull, a11 = 0ull, a12 = 0ull, a13 = 0ull;
        const char* rowp = reinterpret_cast<const char*>(eT + kg * 8);
        #pragma unroll
        for (int c = 0; c < CC; c++) {
            const ulonglong2* q =
                reinterpret_cast<const ulonglong2*>(rowp + c * (RS * 4));
            ulonglong2 v0 = q[0];   // codes k..k+3   (broadcast LDS.128)
            ulonglong2 v1 = q[1];   // codes k+4..k+7
            unsigned long long zd0 = pack2f(zr0[c], zr0[c]);
            unsigned long long zd1 = pack2f(zr1[c], zr1[c]);
            a00 = ffma2(zd0, v0.x, a00);
            a01 = ffma2(zd0, v0.y, a01);
            a02 = ffma2(zd0, v1.x, a02);
            a03 = ffma2(zd0, v1.y, a03);
            a10 = ffma2(zd1, v0.x, a10);
            a11 = ffma2(zd1, v0.y, a11);
            a12 = ffma2(zd1, v1.x, a12);
            a13 = ffma2(zd1, v1.y, a13);
        }
        float d0[8], d1[8];
        unpack2f(a00, d0[0], d0[1]); unpack2f(a01, d0[2], d0[3]);
        unpack2f(a02, d0[4], d0[5]); unpack2f(a03, d0[6], d0[7]);
        unpack2f(a10, d1[0], d1[1]); unpack2f(a11, d1[2], d1[3]);
        unpack2f(a12, d1[4], d1[5]); unpack2f(a13, d1[6], d1[7]);
        int kb = ch * CHUNK + kg * 8;
        #pragma unroll
        for (int j = 0; j < 8; j++) {
            float e2 = e2s[kg * 8 + j];
            float s0 = __fsub_rn(__fadd_rn(zz0, e2), __fmul_rn(2.0f, d0[j]));
            float s1 = __fsub_rn(__fadd_rn(zz1, e2), __fmul_rn(2.0f, d1[j]));
            if (s0 < best0) { best0 = s0; bk0 = kb + j; }
            if (s1 < best1) { best1 = s1; bk1 = kb + j; }
        }
    }

    g_cv[ch * NPIX + p0] = best0;
    g_ck[ch * NPIX + p0] = (unsigned short)bk0;
    g_cv[ch * NPIX + p1] = best1;
    g_ck[ch * NPIX + p1] = (unsigned short)bk1;
}

// ---- K2: merge candidates + emit q/loss/idx; last block finalizes ----------
__global__ void __launch_bounds__(128)
vq_emit(const float* __restrict__ z, const float* __restrict__ emb,
        float* __restrict__ out) {
    __shared__ float reds[4];
    __shared__ int   s_last;
    const int tid = threadIdx.x;
    const int p = blockIdx.x * 128 + tid;
    const int b = p >> 12, hw = p & 4095;

    // merge in ascending-chunk order, strict < => global first-min
    float best = g_cv[p];
    int   bk   = g_ck[p];
    #pragma unroll
    for (int q = 1; q < NCHUNK; q++) {
        float v = g_cv[q * NPIX + p];
        if (v < best) { best = v; bk = g_ck[q * NPIX + p]; }
    }

    const float4* er = reinterpret_cast<const float4*>(emb + (size_t)bk * CC);
    const float* zp = z + (size_t)b * (CC * CHW) + hw;
    float* qp = out + (size_t)b * (CC * CHW) + hw;

    float sumsq = 0.f;
    #pragma unroll
    for (int i = 0; i < 16; i++) {
        float4 e4 = __ldg(er + i);
        float ev[4] = {e4.x, e4.y, e4.z, e4.w};
        #pragma unroll
        for (int j = 0; j < 4; j++) {
            int c = 4 * i + j;
            float zv = zp[c * CHW];
            float dd = __fsub_rn(ev[j], zv);
            sumsq = __fadd_rn(sumsq, __fmul_rn(dd, dd));
            qp[c * CHW] = __fadd_rn(zv, dd);          // fl(z + fl(e - z))
        }
    }
    out[IDX0 + p] = (float)bk;

    #pragma unroll
    for (int o = 16; o; o >>= 1)
        sumsq += __shfl_xor_sync(0xffffffffu, sumsq, o);
    if ((tid & 31) == 0) reds[tid >> 5] = sumsq;
    __syncthreads();
    if (tid == 0) {
        g_part[blockIdx.x] = ((reds[0] + reds[1]) + (reds[2] + reds[3]));
        __threadfence();
        s_last = (atomicAdd(&g_ecnt, 1) == EBLK - 1);
    }
    __syncthreads();
    if (!s_last) return;
    __threadfence();   // acquire: all g_part visible

    // deterministic final sum: 128 threads x 4 partials, fixed tree
    float s = ((g_part[tid] + g_part[tid + 128]) +
               (g_part[tid + 256] + g_part[tid + 384]));
    #pragma unroll
    for (int o = 16; o; o >>= 1)
        s += __shfl_xor_sync(0xffffffffu, s, o);
    if ((tid & 31) == 0) reds[tid >> 5] = s;
    __syncthreads();
    if (tid == 0) {
        float t = ((reds[0] + reds[1]) + (reds[2] + reds[3]));
        float loss = t * (1.0f / (float)Q_ELEMS);
        out[LOSS0] = loss;
        out[LOSS1] = loss;
        g_ecnt = 0;                      // replay-safe reset
    }
}

extern "C" void kernel_launch(void* const* d_in, const int* in_sizes, int n_in,
                              void* d_out, int out_size) {
    const float* z   = (const float*)d_in[0];
    const float* emb = (const float*)d_in[1];
    float* out = (float*)d_out;

    vq_score<<<NCHUNK * NGRP, NTHR>>>(z, emb);
    vq_emit<<<EBLK, 128>>>(z, emb, out);
}

// round 17
// speedup vs baseline: 1.6370x; 1.0459x over previous
#include <cuda_runtime.h>
#include <cstdint>

// ---------------------------------------------------------------------------
// VQ-VAE VectorQuantizer, GB300 sm_103 — bit-exact fp32 reference emulation.
// R17 = R16 scorer (proven, FFMA2 RF-banking floor) + 4-threads-per-pixel
// emit (16 channels each) to fix emit's memory-latency bound (17.5 -> ~7us).
//   zz, e2_k: sequential fp32 mul+add chains, c ascending
//   dot_k:    sequential fp32 FMA chain, c ascending (2 codes per FFMA2 lane)
//   d_k = fl(fl(zz+e2_k) - fl(2*dot_k)); first-min, k ascending
//   q   = fl(z + fl(e - z))
// ---------------------------------------------------------------------------

constexpr int CC     = 64;           // channels
constexpr int CHW    = 4096;         // H*W
constexpr int NPIX   = 65536;        // B*H*W
constexpr int KCB    = 1024;         // codebook entries
constexpr int CHUNK  = 128;          // codes per block
constexpr int NCHUNK = KCB / CHUNK;  // 8
constexpr int NTHR   = 128;          // threads per scorer block
constexpr int GRP    = 256;          // pixels per block (PZ=2)
constexpr int NGRP   = NPIX / GRP;   // 256
constexpr int RS     = 132;          // e_T row stride in floats (pad)

constexpr int EBLK   = 1024;         // emit grid (256 thr, 4 thr/pixel)

constexpr int Q_ELEMS = 4194304;
constexpr int LOSS0   = Q_ELEMS;
constexpr int LOSS1   = Q_ELEMS + 1;
constexpr int IDX0    = Q_ELEMS + 2;

__device__ float          g_cv[NCHUNK * NPIX];   // candidate scores [ch][px]
__device__ unsigned short g_ck[NCHUNK * NPIX];   // candidate global k
__device__ float          g_part[EBLK];
__device__ int            g_ecnt;                // zero-init; reset below

// ---- packed f32x2 helpers --------------------------------------------------
__device__ __forceinline__ unsigned long long pack2f(float lo, float hi) {
    unsigned long long r;
    asm("mov.b64 %0, {%1, %2};" : "=l"(r) : "f"(lo), "f"(hi));
    return r;
}
__device__ __forceinline__ void unpack2f(unsigned long long v, float& lo, float& hi) {
    asm("mov.b64 {%0, %1}, %2;" : "=f"(lo), "=f"(hi) : "l"(v));
}
__device__ __forceinline__ unsigned long long ffma2(unsigned long long a,
                                                    unsigned long long b,
                                                    unsigned long long c) {
    unsigned long long d;
    asm("fma.rn.f32x2 %0, %1, %2, %3;" : "=l"(d) : "l"(a), "l"(b), "l"(c));
    return d;
}

// ---- K1: per-chunk scorer (256 px x 128 codes per block) — proven ----------
__global__ __launch_bounds__(NTHR)
void vq_score(const float* __restrict__ z, const float* __restrict__ emb) {
    __shared__ __align__(16) float eT[CC * RS];   // transposed chunk [c][k]
    __shared__ float e2s[CHUNK];

    const int tid = threadIdx.x;
    const int ch  = blockIdx.x >> 8;      // 0..7 (ascending-k chunks)
    const int grp = blockIdx.x & 255;     // 0..255

    const int p0  = grp * GRP + tid;
    const int p1  = p0 + NTHR;
    const int b0  = p0 >> 12, hw0 = p0 & 4095;
    const int b1  = p1 >> 12, hw1 = p1 & 4095;
    const float* zp0 = z + (size_t)b0 * (CC * CHW) + hw0;
    const float* zp1 = z + (size_t)b1 * (CC * CHW) + hw1;

    float zr0[CC], zr1[CC];
    #pragma unroll
    for (int c = 0; c < CC; c++) zr0[c] = zp0[c * CHW];
    #pragma unroll
    for (int c = 0; c < CC; c++) zr1[c] = zp1[c * CHW];

    float zz0 = 0.f, zz1 = 0.f;
    #pragma unroll
    for (int c = 0; c < CC; c++) zz0 = __fadd_rn(zz0, __fmul_rn(zr0[c], zr0[c]));
    #pragma unroll
    for (int c = 0; c < CC; c++) zz1 = __fadd_rn(zz1, __fmul_rn(zr1[c], zr1[c]));

    // ---- stage + transpose this block's chunk into eT[c][k] ---------------
    const float* ebase = emb + ch * CHUNK * CC;
    #pragma unroll
    for (int it = 0; it < 4; it++) {
        int idx = tid + it * NTHR;        // 0..511
        int k0  = (idx & 31) * 4;
        int c0  = (idx >> 5) * 4;
        float4 r0 = *reinterpret_cast<const float4*>(ebase + (k0 + 0) * CC + c0);
        float4 r1 = *reinterpret_cast<const float4*>(ebase + (k0 + 1) * CC + c0);
        float4 r2 = *reinterpret_cast<const float4*>(ebase + (k0 + 2) * CC + c0);
        float4 r3 = *reinterpret_cast<const float4*>(ebase + (k0 + 3) * CC + c0);
        *reinterpret_cast<float4*>(eT + (c0 + 0) * RS + k0) = make_float4(r0.x, r1.x, r2.x, r3.x);
        *reinterpret_cast<float4*>(eT + (c0 + 1) * RS + k0) = make_float4(r0.y, r1.y, r2.y, r3.y);
        *reinterpret_cast<float4*>(eT + (c0 + 2) * RS + k0) = make_float4(r0.z, r1.z, r2.z, r3.z);
        *reinterpret_cast<float4*>(eT + (c0 + 3) * RS + k0) = make_float4(r0.w, r1.w, r2.w, r3.w);
    }
    __syncthreads();
    {   // exact e2 chain per code (reference mul+add order, c ascending)
        float s = 0.f;
        #pragma unroll
        for (int c = 0; c < CC; c++) {
            float ev = eT[c * RS + tid];   // conflict-free (stride 132)
            s = __fadd_rn(s, __fmul_rn(ev, ev));
        }
        e2s[tid] = s;
    }
    __syncthreads();

    float best0 = 3.4e38f, best1 = 3.4e38f;
    int   bk0 = 0, bk1 = 0;

    #pragma unroll 1
    for (int kg = 0; kg < CHUNK / 8; kg++) {
        unsigned long long a00 = 0ull, a01 = 0ull, a02 = 0ull, a03 = 0ull;
        unsigned long long a10 = 0ull, a11 = 0ull, a12 = 0ull, a13 = 0ull;
        const char* rowp = reinterpret_cast<const char*>(eT + kg * 8);
        #pragma unroll
        for (int c = 0; c < CC; c++) {
            const ulonglong2* q =
                reinterpret_cast<const ulonglong2*>(rowp + c * (RS * 4));
            ulonglong2 v0 = q[0];   // codes k..k+3   (broadcast LDS.128)
            ulonglong2 v1 = q[1];   // codes k+4..k+7
            unsigned long long zd0 = pack2f(zr0[c], zr0[c]);
            unsigned long long zd1 = pack2f(zr1[c], zr1[c]);
            a00 = ffma2(zd0, v0.x, a00);
            a01 = ffma2(zd0, v0.y, a01);
            a02 = ffma2(zd0, v1.x, a02);
            a03 = ffma2(zd0, v1.y, a03);
            a10 = ffma2(zd1, v0.x, a10);
            a11 = ffma2(zd1, v0.y, a11);
            a12 = ffma2(zd1, v1.x, a12);
            a13 = ffma2(zd1, v1.y, a13);
        }
        float d0[8], d1[8];
        unpack2f(a00, d0[0], d0[1]); unpack2f(a01, d0[2], d0[3]);
        unpack2f(a02, d0[4], d0[5]); unpack2f(a03, d0[6], d0[7]);
        unpack2f(a10, d1[0], d1[1]); unpack2f(a11, d1[2], d1[3]);
        unpack2f(a12, d1[4], d1[5]); unpack2f(a13, d1[6], d1[7]);
        int kb = ch * CHUNK + kg * 8;
        #pragma unroll
        for (int j = 0; j < 8; j++) {
            float e2 = e2s[kg * 8 + j];
            float s0 = __fsub_rn(__fadd_rn(zz0, e2), __fmul_rn(2.0f, d0[j]));
            float s1 = __fsub_rn(__fadd_rn(zz1, e2), __fmul_rn(2.0f, d1[j]));
            if (s0 < best0) { best0 = s0; bk0 = kb + j; }
            if (s1 < best1) { best1 = s1; bk1 = kb + j; }
        }
    }

    g_cv[ch * NPIX + p0] = best0;
    g_ck[ch * NPIX + p0] = (unsigned short)bk0;
    g_cv[ch * NPIX + p1] = best1;
    g_ck[ch * NPIX + p1] = (unsigned short)bk1;
}

// ---- K2: merge + emit, 4 threads per pixel (16 channels each) --------------
__global__ void __launch_bounds__(256)
vq_emit(const float* __restrict__ z, const float* __restrict__ emb,
        float* __restrict__ out) {
    __shared__ float reds[8];
    __shared__ int   s_last;
    const int tid  = threadIdx.x;
    const int t    = blockIdx.x * 256 + tid;
    const int p    = t >> 2;              // pixel
    const int part = t & 3;               // channel quarter: c in [part*16, +16)
    const int b    = p >> 12, hw = p & 4095;

    // merge in ascending-chunk order, strict < => global first-min
    // (done redundantly by the 4 threads of a pixel; L2-broadcast loads)
    float best = g_cv[p];
    int   bk   = g_ck[p];
    #pragma unroll
    for (int q = 1; q < NCHUNK; q++) {
        float v = g_cv[q * NPIX + p];
        if (v < best) { best = v; bk = g_ck[q * NPIX + p]; }
    }

    const float4* er = reinterpret_cast<const float4*>(emb + (size_t)bk * CC + part * 16);
    const float* zp = z + (size_t)b * (CC * CHW) + hw + (size_t)(part * 16) * CHW;
    float* qp = out + (size_t)b * (CC * CHW) + hw + (size_t)(part * 16) * CHW;

    float sumsq = 0.f;
    #pragma unroll
    for (int i = 0; i < 4; i++) {
        float4 e4 = __ldg(er + i);
        float ev[4] = {e4.x, e4.y, e4.z, e4.w};
        #pragma unroll
        for (int j = 0; j < 4; j++) {
            int c = 4 * i + j;
            float zv = zp[c * CHW];
            float dd = __fsub_rn(ev[j], zv);
            sumsq = __fadd_rn(sumsq, __fmul_rn(dd, dd));
            qp[c * CHW] = __fadd_rn(zv, dd);          // fl(z + fl(e - z))
        }
    }
    if (part == 0) out[IDX0 + p] = (float)bk;

    #pragma unroll
    for (int o = 16; o; o >>= 1)
        sumsq += __shfl_xor_sync(0xffffffffu, sumsq, o);
    if ((tid & 31) == 0) reds[tid >> 5] = sumsq;
    __syncthreads();
    if (tid == 0) {
        float s = 0.f;
        #pragma unroll
        for (int w = 0; w < 8; w++) s += reds[w];
        g_part[blockIdx.x] = s;
        __threadfence();
        s_last = (atomicAdd(&g_ecnt, 1) == EBLK - 1);
    }
    __syncthreads();
    if (!s_last) return;
    __threadfence();   // acquire: all g_part visible

    // deterministic final sum: 256 threads x 4 partials, fixed tree
    float s = ((g_part[tid] + g_part[tid + 256]) +
               (g_part[tid + 512] + g_part[tid + 768]));
    #pragma unroll
    for (int o = 16; o; o >>= 1)
        s += __shfl_xor_sync(0xffffffffu, s, o);
    if ((tid & 31) == 0) reds[tid >> 5] = s;
    __syncthreads();
    if (tid == 0) {
        float tt = 0.f;
        #pragma unroll
        for (int w = 0; w < 8; w++) tt += reds[w];
        float loss = tt * (1.0f / (float)Q_ELEMS);
        out[LOSS0] = loss;
        out[LOSS1] = loss;
        g_ecnt = 0;                      // replay-safe reset
    }
}

extern "C" void kernel_launch(void* const* d_in, const int* in_sizes, int n_in,
                              void* d_out, int out_size) {
    const float* z   = (const float*)d_in[0];
    const float* emb = (const float*)d_in[1];
    float* out = (float*)d_out;

    vq_score<<<NCHUNK * NGRP, NTHR>>>(z, emb);
    vq_emit<<<EBLK, 256>>>(z, emb, out);
}